// round 6
// baseline (speedup 1.0000x reference)
#include <cuda_runtime.h>

// Problem constants
#define N_TOTAL   32768      // 8 * 16*16*16 rows of z_flat
#define K_CODES   8192
#define C_DIM     256
#define S_SPATIAL 4096       // 16*16*16
#define CS        (C_DIM * S_SPATIAL)

#define BN 128
#define BK 128
#define BC 8

// Output layout in d_out (float32, concatenated reference outputs):
//   [0, 8388608)            : out  [8,256,16,16,16]
//   [8388608]               : loss (scalar)
//   [8388609, 8421377)      : idx  [32768] (as float)
#define OUT_Z_ELEMS 8388608

// Scratch (static device globals - no allocation)
__device__ float g_znorm[N_TOTAL];
__device__ float g_cnorm[K_CODES];
__device__ int   g_idx[N_TOTAL];

// Packed dual-fp32 FMA (Blackwell f32x2 pipe). Each lane is an independent
// fma.rn — bit-identical to two scalar fmaf's.
__device__ __forceinline__ unsigned long long fma2(unsigned long long a,
                                                   unsigned long long b,
                                                   unsigned long long c) {
    unsigned long long d;
    asm("fma.rn.f32x2 %0, %1, %2, %3;" : "=l"(d) : "l"(a), "l"(b), "l"(c));
    return d;
}
__device__ __forceinline__ unsigned long long dup2(float x) {
    unsigned long long d;
    asm("mov.b64 %0, {%1, %1};" : "=l"(d) : "r"(__float_as_uint(x)));
    return d;
}
__device__ __forceinline__ float lo32(unsigned long long v) {
    return __uint_as_float((unsigned)v);
}
__device__ __forceinline__ float hi32(unsigned long long v) {
    return __uint_as_float((unsigned)(v >> 32));
}

__global__ void init_loss_kernel(float* loss) { *loss = 0.0f; }

// grid 320, block 128: blocks [0,256) compute znorm (128 rows each),
// blocks [256,320) compute cnorm (128 codes each, 1 thread per code).
__global__ void norms_kernel(const float* __restrict__ z,
                             const float* __restrict__ cb) {
    if (blockIdx.x < 256) {
        int n0 = blockIdx.x * 128;
        int b  = n0 >> 12;
        int s0 = n0 & 4095;
        const float* zr = z + (size_t)b * CS + s0 + threadIdx.x;
        float sum = 0.0f;
        #pragma unroll 8
        for (int c = 0; c < C_DIM; c++) {
            float v = zr[(size_t)c * S_SPATIAL];
            sum += v * v;
        }
        g_znorm[n0 + threadIdx.x] = sum;
    } else {
        int k = (blockIdx.x - 256) * 128 + threadIdx.x;
        const float4* cr = (const float4*)(cb + (size_t)k * C_DIM);
        float sum = 0.0f;
        #pragma unroll 8
        for (int i = 0; i < C_DIM / 4; i++) {
            float4 v = cr[i];
            sum += v.x * v.x + v.y * v.y + v.z * v.z + v.w * v.w;
        }
        g_cnorm[k] = sum;
    }
}

// Fused GEMM + argmin with packed f32x2 FMAs.
// grid = 256 CTAs (one per 128 rows), block = 256 threads.
// Per-thread 8 rows x 8 cols fragment; cols held as 4 packed f32x2 pairs.
__global__ void __launch_bounds__(256)
argmin_kernel(const float* __restrict__ z,
              const float* __restrict__ cb,
              float* __restrict__ out_idx_f) {
    __shared__ float As[2][BC][132];
    __shared__ float Bs[2][BC][132];
    __shared__ float cns[BK];
    __shared__ float zns[BN];
    __shared__ float redS[BN][17];
    __shared__ int   redI[BN][17];

    int tid = threadIdx.x;
    int n0  = blockIdx.x * BN;
    int b   = n0 >> 12;
    int s0  = n0 & 4095;
    const float* zA = z + (size_t)b * CS + s0;   // + c*S_SPATIAL + s

    int tx = tid & 15;           // k dimension (8 cols each)
    int ty = tid >> 4;           // n dimension (8 rows each)
    int row0 = ty * 8;
    int col0 = tx * 8;

    // global load mappings
    int a_c = tid >> 5;          // 0..7  channel within chunk
    int a_s = (tid & 31) * 4;    // 0..124 spatial offset (float4)
    int b_k = tid >> 1;          // 0..127 code row
    int b_c = (tid & 1) * 4;     // 0 or 4 channel offset (float4)

    if (tid < BN) zns[tid] = g_znorm[n0 + tid];

    float best[8];
    int   bidx[8];
    #pragma unroll
    for (int i = 0; i < 8; i++) { best[i] = 3.4e38f; bidx[i] = 0; }

    for (int kt = 0; kt < K_CODES / BK; kt++) {
        int k0 = kt * BK;
        __syncthreads();   // protect smem reuse across tiles
        if (tid < BK) cns[tid] = g_cnorm[k0 + tid];

        // prologue: chunk 0 -> buffer 0
        float4 ra = *(const float4*)(zA + (size_t)a_c * S_SPATIAL + a_s);
        float4 rb = *(const float4*)(cb + (size_t)(k0 + b_k) * C_DIM + b_c);
        *(float4*)&As[0][a_c][a_s] = ra;
        Bs[0][b_c + 0][b_k] = rb.x;
        Bs[0][b_c + 1][b_k] = rb.y;
        Bs[0][b_c + 2][b_k] = rb.z;
        Bs[0][b_c + 3][b_k] = rb.w;
        __syncthreads();

        unsigned long long acc2[8][4] = {};   // packed (col 2j, col 2j+1)
        int buf = 0;
        for (int cc = 0; cc < C_DIM; cc += BC) {
            int nc = cc + BC;
            float4 na, nb;
            if (nc < C_DIM) {
                na = *(const float4*)(zA + (size_t)(nc + a_c) * S_SPATIAL + a_s);
                nb = *(const float4*)(cb + (size_t)(k0 + b_k) * C_DIM + nc + b_c);
            }
            #pragma unroll
            for (int c = 0; c < BC; c++) {
                float a[8];
                *(float4*)&a[0] = *(float4*)&As[buf][c][row0];
                *(float4*)&a[4] = *(float4*)&As[buf][c][row0 + 4];
                // B pairs read directly as 64-bit packed values (32B aligned)
                ulonglong2 bA = *(const ulonglong2*)&Bs[buf][c][col0];
                ulonglong2 bB = *(const ulonglong2*)&Bs[buf][c][col0 + 4];
                unsigned long long b2[4] = {bA.x, bA.y, bB.x, bB.y};
                #pragma unroll
                for (int i = 0; i < 8; i++) {
                    unsigned long long ad = dup2(a[i]);
                    #pragma unroll
                    for (int j2 = 0; j2 < 4; j2++)
                        acc2[i][j2] = fma2(ad, b2[j2], acc2[i][j2]);
                }
            }
            if (nc < C_DIM) {
                buf ^= 1;
                *(float4*)&As[buf][a_c][a_s] = na;
                Bs[buf][b_c + 0][b_k] = nb.x;
                Bs[buf][b_c + 1][b_k] = nb.y;
                Bs[buf][b_c + 2][b_k] = nb.z;
                Bs[buf][b_c + 3][b_k] = nb.w;
                __syncthreads();
            }
        }

        // epilogue: score = fl(fl(zn + cn) - 2*dot), mimic reference rounding
        #pragma unroll
        for (int i = 0; i < 8; i++) {
            float zni = zns[row0 + i];
            #pragma unroll
            for (int j2 = 0; j2 < 4; j2++) {
                float dlo = lo32(acc2[i][j2]);
                float dhi = hi32(acc2[i][j2]);
                float slo = __fadd_rn(__fadd_rn(zni, cns[col0 + 2 * j2]),
                                      -2.0f * dlo);
                float shi = __fadd_rn(__fadd_rn(zni, cns[col0 + 2 * j2 + 1]),
                                      -2.0f * dhi);
                if (slo < best[i]) {      // strict < => lowest index wins
                    best[i] = slo;
                    bidx[i] = k0 + col0 + 2 * j2;
                }
                if (shi < best[i]) {
                    best[i] = shi;
                    bidx[i] = k0 + col0 + 2 * j2 + 1;
                }
            }
        }
    }

    // cross-thread reduction: 16 tx-groups share each row
    __syncthreads();
    #pragma unroll
    for (int i = 0; i < 8; i++) {
        redS[row0 + i][tx] = best[i];
        redI[row0 + i][tx] = bidx[i];
    }
    __syncthreads();
    if (tid < BN) {
        float bs = redS[tid][0];
        int   bk = redI[tid][0];
        #pragma unroll
        for (int t = 1; t < 16; t++) {
            float s  = redS[tid][t];
            int   k2 = redI[tid][t];
            if (s < bs || (s == bs && k2 < bk)) { bs = s; bk = k2; }
        }
        g_idx[n0 + tid]     = bk;
        out_idx_f[n0 + tid] = (float)bk;
    }
}

// Gather z_q, write straight-through output (zp + (z_q - zp)), accumulate loss.
// grid 128, block 256: one thread per row n, loop over channels.
__global__ void gather_loss_kernel(const float* __restrict__ z,
                                   const float* __restrict__ cb,
                                   float* __restrict__ out,
                                   float* __restrict__ loss) {
    int tid = threadIdx.x;
    int n = blockIdx.x * 256 + tid;
    int b = n >> 12;
    int s = n & 4095;
    int ci = g_idx[n];
    const float*  zr   = z   + (size_t)b * CS + s;
    float*        orow = out + (size_t)b * CS + s;
    const float4* cr   = (const float4*)(cb + (size_t)ci * C_DIM);

    float sum = 0.0f;
    #pragma unroll 4
    for (int c4 = 0; c4 < C_DIM / 4; c4++) {
        float4 q = cr[c4];
        size_t base = (size_t)(c4 * 4) * S_SPATIAL;
        float z0 = zr[base];
        float z1 = zr[base + S_SPATIAL];
        float z2 = zr[base + 2 * S_SPATIAL];
        float z3 = zr[base + 3 * S_SPATIAL];
        // d = fl(z_q - zp); out = fl(zp + d)  (matches straight-through estimator)
        float d0 = __fadd_rn(q.x, -z0);
        float d1 = __fadd_rn(q.y, -z1);
        float d2 = __fadd_rn(q.z, -z2);
        float d3 = __fadd_rn(q.w, -z3);
        orow[base]                 = __fadd_rn(z0, d0);
        orow[base + S_SPATIAL]     = __fadd_rn(z1, d1);
        orow[base + 2 * S_SPATIAL] = __fadd_rn(z2, d2);
        orow[base + 3 * S_SPATIAL] = __fadd_rn(z3, d3);
        sum += d0 * d0 + d1 * d1 + d2 * d2 + d3 * d3;
    }

    // block reduction
    __shared__ float wsum[8];
    #pragma unroll
    for (int off = 16; off > 0; off >>= 1)
        sum += __shfl_down_sync(0xffffffffu, sum, off);
    if ((tid & 31) == 0) wsum[tid >> 5] = sum;
    __syncthreads();
    if (tid == 0) {
        float t = 0.0f;
        #pragma unroll
        for (int w = 0; w < 8; w++) t += wsum[w];
        // loss = mean((zq-zp)^2) + BETA*mean(...) = 2 * sum / (N*C)
        atomicAdd(loss, t * (2.0f / (float)(N_TOTAL * C_DIM)));
    }
}

extern "C" void kernel_launch(void* const* d_in, const int* in_sizes, int n_in,
                              void* d_out, int out_size) {
    (void)in_sizes; (void)n_in; (void)out_size;
    const float* z  = (const float*)d_in[0];
    const float* cb = (const float*)d_in[1];
    float* out  = (float*)d_out;
    float* loss = out + OUT_Z_ELEMS;
    float* idxf = out + OUT_Z_ELEMS + 1;

    init_loss_kernel<<<1, 1>>>(loss);
    norms_kernel<<<320, 128>>>(z, cb);
    argmin_kernel<<<256, 256>>>(z, cb, idxf);
    gather_loss_kernel<<<128, 256>>>(z, cb, out, loss);
}

// round 10
// speedup vs baseline: 1.7946x; 1.7946x over previous
#include <cuda_runtime.h>
#include <cuda_bf16.h>
#include <cstdint>

#define N_TOTAL   32768
#define K_CODES   8192
#define C_DIM     256
#define S_SPATIAL 4096
#define CS        (C_DIM * S_SPATIAL)
#define OUT_Z_ELEMS 8388608

#define M_CTA   256
#define NCH     64
#define NCHUNKS (K_CODES / NCH)     // 128
#define TAU     2.0e-4f
#define ROWPAD  264                  // bf16 elems per padded row (528 B)

// dynamic smem map (bytes)
#define SM_CNS   0                   // float[2][64]
#define SM_A     1024                // 256 * 528 = 135168
#define SM_B0    (SM_A + 135168)     // 64 * 528 = 33792
#define SM_B1    (SM_B0 + 33792)
#define SMEM_BYTES (SM_B1 + 33792)   // 203776

__device__ float g_znorm[N_TOTAL];
__device__ float g_cnorm[K_CODES];
__device__ int   g_idx[N_TOTAL];
__device__ __align__(16) __nv_bfloat16 g_cb16[K_CODES * C_DIM];
__device__ int   g_fix_cnt, g_fs_cnt;
__device__ int   g_fix_row[N_TOTAL];
__device__ int   g_fix_n[N_TOTAL];
__device__ int   g_fix_cand[N_TOTAL][16];
__device__ int   g_fs_row[N_TOTAL];

// ---------- PTX helpers (all sm_80-era: legal at compute_103) ----------
__device__ __forceinline__ uint32_t smem_u32(const void* p) {
    uint32_t a;
    asm("{ .reg .u64 t; cvta.to.shared.u64 t, %1; cvt.u32.u64 %0, t; }" : "=r"(a) : "l"(p));
    return a;
}
__device__ __forceinline__ void ldmx4(uint32_t* r, uint32_t addr) {
    asm volatile("ldmatrix.sync.aligned.m8n8.x4.shared.b16 {%0,%1,%2,%3}, [%4];"
                 : "=r"(r[0]), "=r"(r[1]), "=r"(r[2]), "=r"(r[3]) : "r"(addr));
}
__device__ __forceinline__ void mma16816(float* d, const uint32_t* a,
                                         uint32_t b0, uint32_t b1) {
    asm volatile("mma.sync.aligned.m16n8k16.row.col.f32.bf16.bf16.f32 "
                 "{%0,%1,%2,%3}, {%4,%5,%6,%7}, {%8,%9}, {%0,%1,%2,%3};"
                 : "+f"(d[0]), "+f"(d[1]), "+f"(d[2]), "+f"(d[3])
                 : "r"(a[0]), "r"(a[1]), "r"(a[2]), "r"(a[3]), "r"(b0), "r"(b1));
}
__device__ __forceinline__ void cpasync16(uint32_t dst, const void* src) {
    asm volatile("cp.async.ca.shared.global [%0], [%1], 16;" :: "r"(dst), "l"(src));
}

// ---------- setup ----------
__global__ void init_kernel(float* loss) { *loss = 0.0f; g_fix_cnt = 0; g_fs_cnt = 0; }

__global__ void norms_kernel(const float* __restrict__ z, const float* __restrict__ cb) {
    if (blockIdx.x < 256) {
        int n0 = blockIdx.x * 128, b = n0 >> 12, s0 = n0 & 4095;
        const float* zr = z + (size_t)b * CS + s0 + threadIdx.x;
        float sum = 0.0f;
        #pragma unroll 8
        for (int c = 0; c < C_DIM; c++) { float v = zr[(size_t)c * S_SPATIAL]; sum += v * v; }
        g_znorm[n0 + threadIdx.x] = sum;
    } else {
        int k = (blockIdx.x - 256) * 128 + threadIdx.x;
        const float4* cr = (const float4*)(cb + (size_t)k * C_DIM);
        float sum = 0.0f;
        #pragma unroll 8
        for (int i = 0; i < C_DIM / 4; i++) {
            float4 v = cr[i];
            sum += v.x * v.x + v.y * v.y + v.z * v.z + v.w * v.w;
        }
        g_cnorm[k] = sum;
    }
}

__global__ void cb16_kernel(const float* __restrict__ cb) {
    int i = blockIdx.x * 1024 + threadIdx.x;
    g_cb16[i] = __float2bfloat16_rn(cb[i]);
}

// ---------- main: mma.sync bf16 GEMM + best-4/lane argmin ----------
__global__ void __launch_bounds__(256, 1)
argmin_mma_kernel(const float* __restrict__ z, float* __restrict__ out_idx_f) {
    extern __shared__ char sm[];
    uint32_t smb = smem_u32(sm);
    int tid = threadIdx.x;
    int w = tid >> 5, l = tid & 31;
    int n0 = blockIdx.x * M_CTA;
    int b = n0 >> 12, s0 = n0 & 4095;
    float* cns = (float*)(sm + SM_CNS);

    // ---- fill A: 256 rows (spatial) x 256 ch, bf16, padded rows of 264 ----
    {
        __nv_bfloat16* A = (__nv_bfloat16*)(sm + SM_A);
        const float* zp = z + (size_t)b * CS + s0 + tid;   // row = tid
        #pragma unroll 4
        for (int c = 0; c < C_DIM; c += 2) {
            float v0 = zp[(size_t)c << 12];
            float v1 = zp[(size_t)(c + 1) << 12];
            __nv_bfloat162 pk;
            pk.x = __float2bfloat16_rn(v0);
            pk.y = __float2bfloat16_rn(v1);
            *(__nv_bfloat162*)&A[tid * ROWPAD + c] = pk;
        }
    }

    // per-thread row norms for its 4 row-slots
    float zn4[4];
    #pragma unroll
    for (int s = 0; s < 4; s++) zn4[s] = g_znorm[n0 + w * 32 + s * 8 + (l >> 2)];

    // ldmatrix base addresses (bytes)
    uint32_t aoff0 = smb + SM_A + (uint32_t)((w * 32 + (l & 15)) * 528 + (l >> 4) * 16);
    uint32_t aoff1 = aoff0 + 16u * 528u;
    uint32_t bofs[4];
    #pragma unroll
    for (int p = 0; p < 4; p++)
        bofs[p] = (uint32_t)((16 * p + (l & 15)) * 528 + (l >> 4) * 16);

    // best-4 per row-slot
    float bS[4][4]; int bI[4][4];
    #pragma unroll
    for (int s = 0; s < 4; s++)
        #pragma unroll
        for (int k = 0; k < 4; k++) { bS[s][k] = 3.4e38f; bI[s][k] = 0; }

    auto stage = [&](int chunk) {
        const __nv_bfloat16* src = g_cb16 + (size_t)chunk * NCH * C_DIM;
        uint32_t bb = smb + (uint32_t)((chunk & 1) ? SM_B1 : SM_B0);
        #pragma unroll
        for (int t = 0; t < 8; t++) {
            int idx = t * 256 + tid;           // 0..2047
            int code = idx >> 5, seg = idx & 31;
            cpasync16(bb + (uint32_t)(code * 528 + seg * 16),
                      src + (size_t)code * C_DIM + seg * 8);
        }
        if (tid < NCH) cns[(chunk & 1) * NCH + tid] = g_cnorm[chunk * NCH + tid];
        asm volatile("cp.async.commit_group;" ::: "memory");
    };

    stage(0);
    for (int i = 0; i < NCHUNKS; i++) {
        if (i + 1 < NCHUNKS) {
            stage(i + 1);
            asm volatile("cp.async.wait_group 1;" ::: "memory");
        } else {
            asm volatile("cp.async.wait_group 0;" ::: "memory");
        }
        __syncthreads();

        // ---- GEMM: D[32 rows x 64 codes] per warp ----
        float acc[2][8][4];
        #pragma unroll
        for (int mt = 0; mt < 2; mt++)
            #pragma unroll
            for (int nt = 0; nt < 8; nt++)
                #pragma unroll
                for (int c = 0; c < 4; c++) acc[mt][nt][c] = 0.0f;

        uint32_t bsel = smb + (uint32_t)((i & 1) ? SM_B1 : SM_B0);
        #pragma unroll 4
        for (int ks = 0; ks < 16; ks++) {
            uint32_t ka = (uint32_t)(ks * 32);
            uint32_t a0[4], a1[4];
            ldmx4(a0, aoff0 + ka);
            ldmx4(a1, aoff1 + ka);
            #pragma unroll
            for (int p = 0; p < 4; p++) {
                uint32_t bf[4];
                ldmx4(bf, bsel + bofs[p] + ka);
                mma16816(acc[0][2 * p],     a0, bf[0], bf[2]);
                mma16816(acc[0][2 * p + 1], a0, bf[1], bf[3]);
                mma16816(acc[1][2 * p],     a1, bf[0], bf[2]);
                mma16816(acc[1][2 * p + 1], a1, bf[1], bf[3]);
            }
        }

        // ---- epilogue: scores + best-4 insert ----
        const float* cn = cns + (i & 1) * NCH;
        int j0 = i * NCH;
        #pragma unroll
        for (int nt = 0; nt < 8; nt++) {
            int col0 = nt * 8 + 2 * (l & 3);
            float2 cn2 = *(const float2*)&cn[col0];
            int id0 = j0 + col0;
            #pragma unroll
            for (int mt = 0; mt < 2; mt++) {
                #pragma unroll
                for (int c = 0; c < 4; c++) {
                    int slot = mt * 2 + (c >> 1);
                    float base = zn4[slot] + ((c & 1) ? cn2.y : cn2.x);
                    float s = fmaf(-2.0f, acc[mt][nt][c], base);
                    if (s < bS[slot][3]) {
                        int id = id0 + (c & 1);
                        #pragma unroll
                        for (int k = 0; k < 4; k++) {
                            if (s < bS[slot][k]) {
                                float ts = bS[slot][k]; int ti = bI[slot][k];
                                bS[slot][k] = s; bI[slot][k] = id;
                                s = ts; id = ti;
                            }
                        }
                    }
                }
            }
        }
        __syncthreads();
    }

    // ---- merge 4 lanes per row via smem (reuse B0 region) ----
    float* mergeS = (float*)(sm + SM_B0);
    int*   mergeI = (int*)(sm + SM_B0 + 16384);
    __syncthreads();
    #pragma unroll
    for (int s = 0; s < 4; s++) {
        int row = w * 32 + s * 8 + (l >> 2);
        int base = row * 16 + (l & 3) * 4;
        #pragma unroll
        for (int k = 0; k < 4; k++) { mergeS[base + k] = bS[s][k]; mergeI[base + k] = bI[s][k]; }
    }
    __syncthreads();

    // ---- classify: one row per thread ----
    {
        int r = tid, base = r * 16, row = n0 + r;
        float mn = 3.4e38f;
        #pragma unroll
        for (int k = 0; k < 16; k++) mn = fminf(mn, mergeS[base + k]);
        float lim = mn + TAU;
        bool fs = false;
        #pragma unroll
        for (int q = 0; q < 4; q++) if (mergeS[base + q * 4 + 3] <= lim) fs = true;
        if (fs) {
            int p = atomicAdd(&g_fs_cnt, 1);
            g_fs_row[p] = row;
        } else {
            int cnt = 0; float bs = 3.4e38f; int bi = 0x7fffffff;
            #pragma unroll
            for (int k = 0; k < 16; k++) {
                float s = mergeS[base + k]; int id = mergeI[base + k];
                if (s <= lim) cnt++;
                if (s < bs || (s == bs && id < bi)) { bs = s; bi = id; }
            }
            if (cnt == 1) {
                g_idx[row] = bi;
                out_idx_f[row] = (float)bi;
            } else {
                int p = atomicAdd(&g_fix_cnt, 1);
                g_fix_row[p] = row; g_fix_n[p] = cnt;
                int c2 = 0;
                for (int k = 0; k < 16; k++)
                    if (mergeS[base + k] <= lim) g_fix_cand[p][c2++] = mergeI[base + k];
            }
        }
    }
}

// ---------- fixups (exact reference fp32 chain) ----------
__global__ void fixup_cand_kernel(const float* __restrict__ z, const float* __restrict__ cb,
                                  float* __restrict__ out_idx_f) {
    int cnt = g_fix_cnt;
    int wid = threadIdx.x >> 5, lid = threadIdx.x & 31;
    for (int rec = blockIdx.x * 4 + wid; rec < cnt; rec += gridDim.x * 4) {
        int row = g_fix_row[rec], nc = g_fix_n[rec];
        float s = 3.4e38f; int ci = 0x7fffffff;
        if (lid < nc) {
            ci = g_fix_cand[rec][lid];
            const float* zr = z + (size_t)(row >> 12) * CS + (row & 4095);
            const float* cr = cb + (size_t)ci * C_DIM;
            float dot = 0.0f;
            #pragma unroll 8
            for (int c = 0; c < C_DIM; c++) dot = fmaf(zr[(size_t)c << 12], cr[c], dot);
            s = __fadd_rn(__fadd_rn(g_znorm[row], g_cnorm[ci]), -2.0f * dot);
        }
        #pragma unroll
        for (int off = 16; off > 0; off >>= 1) {
            float so = __shfl_down_sync(0xffffffffu, s, off);
            int   io = __shfl_down_sync(0xffffffffu, ci, off);
            if (so < s || (so == s && io < ci)) { s = so; ci = io; }
        }
        if (lid == 0) { g_idx[row] = ci; out_idx_f[row] = (float)ci; }
    }
}

__global__ void fullscan_kernel(const float* __restrict__ z, const float* __restrict__ cb,
                                float* __restrict__ out_idx_f) {
    __shared__ float zrow[C_DIM];
    __shared__ float sS[256]; __shared__ int sI[256];
    int cnt = g_fs_cnt, tid = threadIdx.x;
    for (int q = blockIdx.x; q < cnt; q += gridDim.x) {
        int row = g_fs_row[q];
        const float* zr = z + (size_t)(row >> 12) * CS + (row & 4095);
        zrow[tid] = zr[(size_t)tid << 12];
        __syncthreads();
        float zn = g_znorm[row];
        float bs = 3.4e38f; int bi = 0;
        for (int j = tid; j < K_CODES; j += 256) {
            const float* cr = cb + (size_t)j * C_DIM;
            float dot = 0.0f;
            #pragma unroll 8
            for (int c = 0; c < C_DIM; c++) dot = fmaf(zrow[c], cr[c], dot);
            float s = __fadd_rn(__fadd_rn(zn, g_cnorm[j]), -2.0f * dot);
            if (s < bs) { bs = s; bi = j; }
        }
        sS[tid] = bs; sI[tid] = bi;
        __syncthreads();
        for (int off = 128; off > 0; off >>= 1) {
            if (tid < off) {
                float s2 = sS[tid + off]; int i2 = sI[tid + off];
                if (s2 < sS[tid] || (s2 == sS[tid] && i2 < sI[tid])) { sS[tid] = s2; sI[tid] = i2; }
            }
            __syncthreads();
        }
        if (tid == 0) { g_idx[row] = sI[0]; out_idx_f[row] = (float)sI[0]; }
        __syncthreads();
    }
}

// ---------- gather + loss ----------
__global__ void gather_loss_kernel(const float* __restrict__ z, const float* __restrict__ cb,
                                   float* __restrict__ out, float* __restrict__ loss) {
    int tid = threadIdx.x;
    int n = blockIdx.x * 256 + tid;
    int b = n >> 12, s = n & 4095;
    int ci = g_idx[n];
    const float* zr = z + (size_t)b * CS + s;
    float* orow = out + (size_t)b * CS + s;
    const float4* cr = (const float4*)(cb + (size_t)ci * C_DIM);

    float sum = 0.0f;
    #pragma unroll 4
    for (int c4 = 0; c4 < C_DIM / 4; c4++) {
        float4 q = cr[c4];
        size_t base = (size_t)(c4 * 4) * S_SPATIAL;
        float z0 = zr[base], z1 = zr[base + S_SPATIAL];
        float z2 = zr[base + 2 * S_SPATIAL], z3 = zr[base + 3 * S_SPATIAL];
        float d0 = __fadd_rn(q.x, -z0), d1 = __fadd_rn(q.y, -z1);
        float d2 = __fadd_rn(q.z, -z2), d3 = __fadd_rn(q.w, -z3);
        orow[base]                 = __fadd_rn(z0, d0);
        orow[base + S_SPATIAL]     = __fadd_rn(z1, d1);
        orow[base + 2 * S_SPATIAL] = __fadd_rn(z2, d2);
        orow[base + 3 * S_SPATIAL] = __fadd_rn(z3, d3);
        sum += d0 * d0 + d1 * d1 + d2 * d2 + d3 * d3;
    }
    __shared__ float wsum[8];
    #pragma unroll
    for (int off = 16; off > 0; off >>= 1) sum += __shfl_down_sync(0xffffffffu, sum, off);
    if ((tid & 31) == 0) wsum[tid >> 5] = sum;
    __syncthreads();
    if (tid == 0) {
        float t = 0.0f;
        #pragma unroll
        for (int w = 0; w < 8; w++) t += wsum[w];
        atomicAdd(loss, t * (2.0f / (float)(N_TOTAL * C_DIM)));
    }
}

extern "C" void kernel_launch(void* const* d_in, const int* in_sizes, int n_in,
                              void* d_out, int out_size) {
    (void)in_sizes; (void)n_in; (void)out_size;
    const float* z  = (const float*)d_in[0];
    const float* cb = (const float*)d_in[1];
    float* out  = (float*)d_out;
    float* loss = out + OUT_Z_ELEMS;
    float* idxf = out + OUT_Z_ELEMS + 1;

    // Not a stream op: safe under graph capture, idempotent, no static state.
    cudaFuncSetAttribute(argmin_mma_kernel,
                         cudaFuncAttributeMaxDynamicSharedMemorySize, SMEM_BYTES);

    init_kernel<<<1, 1>>>(loss);
    norms_kernel<<<320, 128>>>(z, cb);
    cb16_kernel<<<2048, 1024>>>(cb);
    argmin_mma_kernel<<<128, 256, SMEM_BYTES>>>(z, idxf);
    fixup_cand_kernel<<<256, 128>>>(z, cb, idxf);
    fullscan_kernel<<<64, 256>>>(z, cb, idxf);
    gather_loss_kernel<<<128, 256>>>(z, cb, out, loss);
}

// round 11
// speedup vs baseline: 1.9715x; 1.0986x over previous
#include <cuda_runtime.h>
#include <cuda_bf16.h>
#include <cstdint>

#define N_TOTAL   32768
#define K_CODES   8192
#define C_DIM     256
#define S_SPATIAL 4096
#define CS        (C_DIM * S_SPATIAL)
#define OUT_Z_ELEMS 8388608

#define M_CTA   256
#define NCH     64
#define NCHUNKS (K_CODES / NCH)     // 128
#define TAU     2.0e-4f
#define ROWPAD  264                  // bf16 elems per padded row (528 B)

// dynamic smem map (bytes)
#define SM_CNS   0                   // float[2][64]
#define SM_A     1024                // 256 * 528 = 135168
#define SM_B0    (SM_A + 135168)     // 64 * 528 = 33792
#define SM_B1    (SM_B0 + 33792)
#define SMEM_BYTES (SM_B1 + 33792)   // 203776

__device__ float g_znorm[N_TOTAL];
__device__ float g_cnorm[K_CODES];
__device__ int   g_idx[N_TOTAL];
__device__ __align__(16) __nv_bfloat16 g_cb16[K_CODES * C_DIM];
__device__ int   g_fix_cnt, g_fs_cnt;
__device__ int   g_fix_row[N_TOTAL];
__device__ int   g_fix_n[N_TOTAL];
__device__ int   g_fix_cand[N_TOTAL][16];
__device__ int   g_fs_row[N_TOTAL];

// ---------- PTX helpers (all sm_80-era: legal at compute_103) ----------
__device__ __forceinline__ uint32_t smem_u32(const void* p) {
    uint32_t a;
    asm("{ .reg .u64 t; cvta.to.shared.u64 t, %1; cvt.u32.u64 %0, t; }" : "=r"(a) : "l"(p));
    return a;
}
__device__ __forceinline__ void ldmx4(uint32_t* r, uint32_t addr) {
    asm volatile("ldmatrix.sync.aligned.m8n8.x4.shared.b16 {%0,%1,%2,%3}, [%4];"
                 : "=r"(r[0]), "=r"(r[1]), "=r"(r[2]), "=r"(r[3]) : "r"(addr));
}
__device__ __forceinline__ void mma16816(float* d, const uint32_t* a,
                                         uint32_t b0, uint32_t b1) {
    asm volatile("mma.sync.aligned.m16n8k16.row.col.f32.bf16.bf16.f32 "
                 "{%0,%1,%2,%3}, {%4,%5,%6,%7}, {%8,%9}, {%0,%1,%2,%3};"
                 : "+f"(d[0]), "+f"(d[1]), "+f"(d[2]), "+f"(d[3])
                 : "r"(a[0]), "r"(a[1]), "r"(a[2]), "r"(a[3]), "r"(b0), "r"(b1));
}
__device__ __forceinline__ void cpasync16(uint32_t dst, const void* src) {
    asm volatile("cp.async.ca.shared.global [%0], [%1], 16;" :: "r"(dst), "l"(src));
}

// ---------- setup ----------
__global__ void init_kernel(float* loss) { *loss = 0.0f; g_fix_cnt = 0; g_fs_cnt = 0; }

__global__ void norms_kernel(const float* __restrict__ z, const float* __restrict__ cb) {
    if (blockIdx.x < 256) {
        int n0 = blockIdx.x * 128, b = n0 >> 12, s0 = n0 & 4095;
        const float* zr = z + (size_t)b * CS + s0 + threadIdx.x;
        float sum = 0.0f;
        #pragma unroll 8
        for (int c = 0; c < C_DIM; c++) { float v = zr[(size_t)c * S_SPATIAL]; sum += v * v; }
        g_znorm[n0 + threadIdx.x] = sum;
    } else {
        int k = (blockIdx.x - 256) * 128 + threadIdx.x;
        const float4* cr = (const float4*)(cb + (size_t)k * C_DIM);
        float sum = 0.0f;
        #pragma unroll 8
        for (int i = 0; i < C_DIM / 4; i++) {
            float4 v = cr[i];
            sum += v.x * v.x + v.y * v.y + v.z * v.z + v.w * v.w;
        }
        g_cnorm[k] = sum;
    }
}

__global__ void cb16_kernel(const float* __restrict__ cb) {
    int i = blockIdx.x * 1024 + threadIdx.x;
    g_cb16[i] = __float2bfloat16_rn(cb[i]);
}

// ---------- main: mma.sync bf16 GEMM, 16 warps, 16-row m-tile per warp ----------
__global__ void __launch_bounds__(512, 1)
argmin_mma_kernel(const float* __restrict__ z, float* __restrict__ out_idx_f) {
    extern __shared__ char sm[];
    uint32_t smb = smem_u32(sm);
    int tid = threadIdx.x;
    int w = tid >> 5, l = tid & 31;           // 16 warps
    int n0 = blockIdx.x * M_CTA;
    int b = n0 >> 12, s0 = n0 & 4095;
    float* cns = (float*)(sm + SM_CNS);

    // ---- fill A: 256 rows x 256 ch bf16, padded rows of 264; 2 threads/row ----
    {
        __nv_bfloat16* A = (__nv_bfloat16*)(sm + SM_A);
        int row = tid & 255;
        int ch0 = (tid >> 8) * 128;
        const float* zp = z + (size_t)b * CS + s0 + row;
        #pragma unroll 4
        for (int c = ch0; c < ch0 + 128; c += 2) {
            float v0 = zp[(size_t)c << 12];
            float v1 = zp[(size_t)(c + 1) << 12];
            __nv_bfloat162 pk;
            pk.x = __float2bfloat16_rn(v0);
            pk.y = __float2bfloat16_rn(v1);
            *(__nv_bfloat162*)&A[row * ROWPAD + c] = pk;
        }
    }

    // per-thread row norms for its 2 row-slots (warp owns rows [w*16, w*16+16))
    float zn2[2];
    #pragma unroll
    for (int s = 0; s < 2; s++) zn2[s] = g_znorm[n0 + w * 16 + s * 8 + (l >> 2)];

    // ldmatrix base addresses (bytes)
    uint32_t aoff = smb + SM_A + (uint32_t)((w * 16 + (l & 15)) * 528 + (l >> 4) * 16);
    uint32_t bofs[4];
    #pragma unroll
    for (int p = 0; p < 4; p++)
        bofs[p] = (uint32_t)((16 * p + (l & 15)) * 528 + (l >> 4) * 16);

    // best-4 per row-slot
    float bS[2][4]; int bI[2][4];
    #pragma unroll
    for (int s = 0; s < 2; s++)
        #pragma unroll
        for (int k = 0; k < 4; k++) { bS[s][k] = 3.4e38f; bI[s][k] = 0; }

    auto stage = [&](int chunk) {
        const __nv_bfloat16* src = g_cb16 + (size_t)chunk * NCH * C_DIM;
        uint32_t bb = smb + (uint32_t)((chunk & 1) ? SM_B1 : SM_B0);
        #pragma unroll
        for (int t = 0; t < 4; t++) {
            int idx = t * 512 + tid;           // 0..2047
            int code = idx >> 5, seg = idx & 31;
            cpasync16(bb + (uint32_t)(code * 528 + seg * 16),
                      src + (size_t)code * C_DIM + seg * 8);
        }
        if (tid < NCH) cns[(chunk & 1) * NCH + tid] = g_cnorm[chunk * NCH + tid];
        asm volatile("cp.async.commit_group;" ::: "memory");
    };

    stage(0);
    for (int i = 0; i < NCHUNKS; i++) {
        if (i + 1 < NCHUNKS) {
            stage(i + 1);
            asm volatile("cp.async.wait_group 1;" ::: "memory");
        } else {
            asm volatile("cp.async.wait_group 0;" ::: "memory");
        }
        __syncthreads();

        // ---- GEMM: D[16 rows x 64 codes] per warp ----
        float acc[8][4];
        #pragma unroll
        for (int nt = 0; nt < 8; nt++)
            #pragma unroll
            for (int c = 0; c < 4; c++) acc[nt][c] = 0.0f;

        uint32_t bsel = smb + (uint32_t)((i & 1) ? SM_B1 : SM_B0);
        #pragma unroll 4
        for (int ks = 0; ks < 16; ks++) {
            uint32_t ka = (uint32_t)(ks * 32);
            uint32_t a0[4];
            ldmx4(a0, aoff + ka);
            #pragma unroll
            for (int p = 0; p < 4; p++) {
                uint32_t bf[4];
                ldmx4(bf, bsel + bofs[p] + ka);
                mma16816(acc[2 * p],     a0, bf[0], bf[2]);
                mma16816(acc[2 * p + 1], a0, bf[1], bf[3]);
            }
        }

        // ---- epilogue: scores + best-4 insert ----
        const float* cn = cns + (i & 1) * NCH;
        int j0 = i * NCH;
        #pragma unroll
        for (int nt = 0; nt < 8; nt++) {
            int col0 = nt * 8 + 2 * (l & 3);
            float2 cn2 = *(const float2*)&cn[col0];
            int id0 = j0 + col0;
            #pragma unroll
            for (int c = 0; c < 4; c++) {
                int slot = c >> 1;
                float base = zn2[slot] + ((c & 1) ? cn2.y : cn2.x);
                float s = fmaf(-2.0f, acc[nt][c], base);
                if (s < bS[slot][3]) {
                    int id = id0 + (c & 1);
                    #pragma unroll
                    for (int k = 0; k < 4; k++) {
                        if (s < bS[slot][k]) {
                            float ts = bS[slot][k]; int ti = bI[slot][k];
                            bS[slot][k] = s; bI[slot][k] = id;
                            s = ts; id = ti;
                        }
                    }
                }
            }
        }
        __syncthreads();
    }

    // ---- merge 4 lanes per row via smem (reuse B0 region) ----
    float* mergeS = (float*)(sm + SM_B0);
    int*   mergeI = (int*)(sm + SM_B0 + 16384);
    __syncthreads();
    #pragma unroll
    for (int s = 0; s < 2; s++) {
        int row = w * 16 + s * 8 + (l >> 2);
        int base = row * 16 + (l & 3) * 4;
        #pragma unroll
        for (int k = 0; k < 4; k++) { mergeS[base + k] = bS[s][k]; mergeI[base + k] = bI[s][k]; }
    }
    __syncthreads();

    // ---- classify: one row per thread (threads 0..255) ----
    if (tid < 256) {
        int r = tid, base = r * 16, row = n0 + r;
        float mn = 3.4e38f;
        #pragma unroll
        for (int k = 0; k < 16; k++) mn = fminf(mn, mergeS[base + k]);
        float lim = mn + TAU;
        bool fs = false;
        #pragma unroll
        for (int q = 0; q < 4; q++) if (mergeS[base + q * 4 + 3] <= lim) fs = true;
        if (fs) {
            int p = atomicAdd(&g_fs_cnt, 1);
            g_fs_row[p] = row;
        } else {
            int cnt = 0; float bs = 3.4e38f; int bi = 0x7fffffff;
            #pragma unroll
            for (int k = 0; k < 16; k++) {
                float s = mergeS[base + k]; int id = mergeI[base + k];
                if (s <= lim) cnt++;
                if (s < bs || (s == bs && id < bi)) { bs = s; bi = id; }
            }
            if (cnt == 1) {
                g_idx[row] = bi;
                out_idx_f[row] = (float)bi;
            } else {
                int p = atomicAdd(&g_fix_cnt, 1);
                g_fix_row[p] = row; g_fix_n[p] = cnt;
                int c2 = 0;
                for (int k = 0; k < 16; k++)
                    if (mergeS[base + k] <= lim) g_fix_cand[p][c2++] = mergeI[base + k];
            }
        }
    }
}

// ---------- fixups (exact reference fp32 chain) ----------
__global__ void fixup_cand_kernel(const float* __restrict__ z, const float* __restrict__ cb,
                                  float* __restrict__ out_idx_f) {
    int cnt = g_fix_cnt;
    int wid = threadIdx.x >> 5, lid = threadIdx.x & 31;
    for (int rec = blockIdx.x * 4 + wid; rec < cnt; rec += gridDim.x * 4) {
        int row = g_fix_row[rec], nc = g_fix_n[rec];
        float s = 3.4e38f; int ci = 0x7fffffff;
        if (lid < nc) {
            ci = g_fix_cand[rec][lid];
            const float* zr = z + (size_t)(row >> 12) * CS + (row & 4095);
            const float* cr = cb + (size_t)ci * C_DIM;
            float dot = 0.0f;
            #pragma unroll 8
            for (int c = 0; c < C_DIM; c++) dot = fmaf(zr[(size_t)c << 12], cr[c], dot);
            s = __fadd_rn(__fadd_rn(g_znorm[row], g_cnorm[ci]), -2.0f * dot);
        }
        #pragma unroll
        for (int off = 16; off > 0; off >>= 1) {
            float so = __shfl_down_sync(0xffffffffu, s, off);
            int   io = __shfl_down_sync(0xffffffffu, ci, off);
            if (so < s || (so == s && io < ci)) { s = so; ci = io; }
        }
        if (lid == 0) { g_idx[row] = ci; out_idx_f[row] = (float)ci; }
    }
}

__global__ void fullscan_kernel(const float* __restrict__ z, const float* __restrict__ cb,
                                float* __restrict__ out_idx_f) {
    __shared__ float zrow[C_DIM];
    __shared__ float sS[256]; __shared__ int sI[256];
    int cnt = g_fs_cnt, tid = threadIdx.x;
    for (int q = blockIdx.x; q < cnt; q += gridDim.x) {
        int row = g_fs_row[q];
        const float* zr = z + (size_t)(row >> 12) * CS + (row & 4095);
        zrow[tid] = zr[(size_t)tid << 12];
        __syncthreads();
        float zn = g_znorm[row];
        float bs = 3.4e38f; int bi = 0;
        for (int j = tid; j < K_CODES; j += 256) {
            const float* cr = cb + (size_t)j * C_DIM;
            float dot = 0.0f;
            #pragma unroll 8
            for (int c = 0; c < C_DIM; c++) dot = fmaf(zrow[c], cr[c], dot);
            float s = __fadd_rn(__fadd_rn(zn, g_cnorm[j]), -2.0f * dot);
            if (s < bs) { bs = s; bi = j; }
        }
        sS[tid] = bs; sI[tid] = bi;
        __syncthreads();
        for (int off = 128; off > 0; off >>= 1) {
            if (tid < off) {
                float s2 = sS[tid + off]; int i2 = sI[tid + off];
                if (s2 < sS[tid] || (s2 == sS[tid] && i2 < sI[tid])) { sS[tid] = s2; sI[tid] = i2; }
            }
            __syncthreads();
        }
        if (tid == 0) { g_idx[row] = sI[0]; out_idx_f[row] = (float)sI[0]; }
        __syncthreads();
    }
}

// ---------- gather + loss ----------
__global__ void gather_loss_kernel(const float* __restrict__ z, const float* __restrict__ cb,
                                   float* __restrict__ out, float* __restrict__ loss) {
    int tid = threadIdx.x;
    int n = blockIdx.x * 256 + tid;
    int b = n >> 12, s = n & 4095;
    int ci = g_idx[n];
    const float* zr = z + (size_t)b * CS + s;
    float* orow = out + (size_t)b * CS + s;
    const float4* cr = (const float4*)(cb + (size_t)ci * C_DIM);

    float sum = 0.0f;
    #pragma unroll 4
    for (int c4 = 0; c4 < C_DIM / 4; c4++) {
        float4 q = cr[c4];
        size_t base = (size_t)(c4 * 4) * S_SPATIAL;
        float z0 = zr[base], z1 = zr[base + S_SPATIAL];
        float z2 = zr[base + 2 * S_SPATIAL], z3 = zr[base + 3 * S_SPATIAL];
        float d0 = __fadd_rn(q.x, -z0), d1 = __fadd_rn(q.y, -z1);
        float d2 = __fadd_rn(q.z, -z2), d3 = __fadd_rn(q.w, -z3);
        orow[base]                 = __fadd_rn(z0, d0);
        orow[base + S_SPATIAL]     = __fadd_rn(z1, d1);
        orow[base + 2 * S_SPATIAL] = __fadd_rn(z2, d2);
        orow[base + 3 * S_SPATIAL] = __fadd_rn(z3, d3);
        sum += d0 * d0 + d1 * d1 + d2 * d2 + d3 * d3;
    }
    __shared__ float wsum[8];
    #pragma unroll
    for (int off = 16; off > 0; off >>= 1) sum += __shfl_down_sync(0xffffffffu, sum, off);
    if ((tid & 31) == 0) wsum[tid >> 5] = sum;
    __syncthreads();
    if (tid == 0) {
        float t = 0.0f;
        #pragma unroll
        for (int w = 0; w < 8; w++) t += wsum[w];
        atomicAdd(loss, t * (2.0f / (float)(N_TOTAL * C_DIM)));
    }
}

extern "C" void kernel_launch(void* const* d_in, const int* in_sizes, int n_in,
                              void* d_out, int out_size) {
    (void)in_sizes; (void)n_in; (void)out_size;
    const float* z  = (const float*)d_in[0];
    const float* cb = (const float*)d_in[1];
    float* out  = (float*)d_out;
    float* loss = out + OUT_Z_ELEMS;
    float* idxf = out + OUT_Z_ELEMS + 1;

    // Not a stream op: safe under graph capture, idempotent, no static state.
    cudaFuncSetAttribute(argmin_mma_kernel,
                         cudaFuncAttributeMaxDynamicSharedMemorySize, SMEM_BYTES);

    init_kernel<<<1, 1>>>(loss);
    norms_kernel<<<320, 128>>>(z, cb);
    cb16_kernel<<<2048, 1024>>>(cb);
    argmin_mma_kernel<<<128, 512, SMEM_BYTES>>>(z, idxf);
    fixup_cand_kernel<<<256, 128>>>(z, cb, idxf);
    fullscan_kernel<<<64, 256>>>(z, cb, idxf);
    gather_loss_kernel<<<128, 256>>>(z, cb, out, loss);
}